// round 1
// baseline (speedup 1.0000x reference)
#include <cuda_runtime.h>
#include <math_constants.h>

// Problem constants (shapes fixed by setup_inputs)
#define N_PRE 8192
#define N_CUR 16384
#define KNN   8
#define P1    4                  // partitions over pre for the argmin kernel
#define P2    8                  // partitions over cur for the top-8 kernel
#define TILE1 (N_PRE / P1)       // 2048 candidates per block
#define TILE2 (N_CUR / P2)       // 2048 candidates per block
#define NTHREADS 256

// Scratch (no allocations allowed — device globals)
__device__ int   g_cur2pre[N_CUR];
__device__ float g_p1_key[P1 * N_CUR];
__device__ int   g_p1_idx[P1 * N_CUR];
__device__ float g_p2_key[P2 * KNN * N_PRE];
__device__ int   g_p2_idx[P2 * KNN * N_PRE];

// ---------------------------------------------------------------------------
// Kernel 1: partial argmin over pre for each cur point.
// Block = 256 cur queries; blockIdx.y selects a 2048-wide pre partition held
// entirely in SMEM as float4 (x, y, z, |p|^2). All threads walk the same
// candidate -> LDS.128 broadcast (conflict-free, N=1).
// Ordering key: |p|^2 - 2*q.p  (== sqdist - |q|^2, same ordering).
// ---------------------------------------------------------------------------
__global__ __launch_bounds__(NTHREADS)
void k1_argmin(const float* __restrict__ pre, const float* __restrict__ cur) {
    __shared__ float4 tile[TILE1];
    const int part = blockIdx.y;
    const int base = part * TILE1;

    for (int t = threadIdx.x; t < TILE1; t += NTHREADS) {
        float x = pre[base + t];
        float y = pre[N_PRE + base + t];
        float z = pre[2 * N_PRE + base + t];
        float na = fmaf(z, z, fmaf(y, y, x * x));
        tile[t] = make_float4(x, y, z, na);
    }
    __syncthreads();

    const int j = blockIdx.x * NTHREADS + threadIdx.x;
    const float qx = cur[j];
    const float qy = cur[N_CUR + j];
    const float qz = cur[2 * N_CUR + j];

    float bk = CUDART_INF_F;
    int   bi = base;
#pragma unroll 8
    for (int t = 0; t < TILE1; ++t) {
        float4 c  = tile[t];
        float dot = fmaf(qz, c.z, fmaf(qy, c.y, qx * c.x));
        float key = fmaf(-2.0f, dot, c.w);
        if (key < bk) { bk = key; bi = base + t; }  // strict < : lowest index wins
    }
    g_p1_key[part * N_CUR + j] = bk;
    g_p1_idx[part * N_CUR + j] = bi;
}

// Reduce the P1 partials (ascending partition order preserves argmin tie rule).
__global__ __launch_bounds__(NTHREADS)
void k1_reduce() {
    const int j = blockIdx.x * NTHREADS + threadIdx.x;
    float bk = g_p1_key[j];
    int   bi = g_p1_idx[j];
#pragma unroll
    for (int p = 1; p < P1; ++p) {
        float k2 = g_p1_key[p * N_CUR + j];
        if (k2 < bk) { bk = k2; bi = g_p1_idx[p * N_CUR + j]; }
    }
    g_cur2pre[j] = bi;
}

// ---------------------------------------------------------------------------
// Kernel 2: partial top-8 (smallest keys) over cur for each pre point.
// Same broadcast-candidate structure; each thread keeps a sorted 8-entry list
// in registers (fully unrolled -> no local memory).
// ---------------------------------------------------------------------------
__global__ __launch_bounds__(NTHREADS)
void k2_topk(const float* __restrict__ pre, const float* __restrict__ cur) {
    __shared__ float4 tile[TILE2];
    const int part = blockIdx.y;
    const int base = part * TILE2;

    for (int t = threadIdx.x; t < TILE2; t += NTHREADS) {
        float x = cur[base + t];
        float y = cur[N_CUR + base + t];
        float z = cur[2 * N_CUR + base + t];
        float nc = fmaf(z, z, fmaf(y, y, x * x));
        tile[t] = make_float4(x, y, z, nc);
    }
    __syncthreads();

    const int i = blockIdx.x * NTHREADS + threadIdx.x;
    const float qx = pre[i];
    const float qy = pre[N_PRE + i];
    const float qz = pre[2 * N_PRE + i];

    float d[KNN];
    int   id[KNN];
#pragma unroll
    for (int k = 0; k < KNN; ++k) { d[k] = CUDART_INF_F; id[k] = 0; }

#pragma unroll 4
    for (int t = 0; t < TILE2; ++t) {
        float4 c  = tile[t];
        float dot = fmaf(qz, c.z, fmaf(qy, c.y, qx * c.x));
        float key = fmaf(-2.0f, dot, c.w);
        if (key < d[KNN - 1]) {                 // rare after warm-up (~44/2048)
            d[KNN - 1]  = key;
            id[KNN - 1] = base + t;
#pragma unroll
            for (int s = KNN - 1; s > 0; --s) { // bubble new element into place
                if (d[s] < d[s - 1]) {
                    float tf = d[s]; d[s] = d[s - 1]; d[s - 1] = tf;
                    int   ti = id[s]; id[s] = id[s - 1]; id[s - 1] = ti;
                }
            }
        }
    }
#pragma unroll
    for (int k = 0; k < KNN; ++k) {             // transposed layout: coalesced
        g_p2_key[(part * KNN + k) * N_PRE + i] = d[k];
        g_p2_idx[(part * KNN + k) * N_PRE + i] = id[k];
    }
}

// ---------------------------------------------------------------------------
// Kernel 3: merge P2 x 8 partial candidates -> global top-8, then the masked
// mean distance:  out[i] = sum_k dist(pre_i, knn_k) * [cur2pre[knn_k]==i] / ups[i]
// ---------------------------------------------------------------------------
__global__ __launch_bounds__(NTHREADS)
void k3_final(const float* __restrict__ pre, const float* __restrict__ cur,
              const float* __restrict__ ups, float* __restrict__ out) {
    const int i = blockIdx.x * NTHREADS + threadIdx.x;

    float d[KNN];
    int   id[KNN];
#pragma unroll
    for (int k = 0; k < KNN; ++k) { d[k] = CUDART_INF_F; id[k] = 0; }

#pragma unroll
    for (int p = 0; p < P2; ++p) {
#pragma unroll
        for (int k = 0; k < KNN; ++k) {
            float key = g_p2_key[(p * KNN + k) * N_PRE + i];
            if (key < d[KNN - 1]) {
                int idx = g_p2_idx[(p * KNN + k) * N_PRE + i];
                d[KNN - 1]  = key;
                id[KNN - 1] = idx;
#pragma unroll
                for (int s = KNN - 1; s > 0; --s) {
                    if (d[s] < d[s - 1]) {
                        float tf = d[s]; d[s] = d[s - 1]; d[s - 1] = tf;
                        int   ti = id[s]; id[s] = id[s - 1]; id[s - 1] = ti;
                    }
                }
            }
        }
    }

    const float px = pre[i];
    const float py = pre[N_PRE + i];
    const float pz = pre[2 * N_PRE + i];

    float sum = 0.0f;
#pragma unroll
    for (int k = 0; k < KNN; ++k) {
        int j = id[k];
        float dx = cur[j] - px;
        float dy = cur[N_CUR + j] - py;
        float dz = cur[2 * N_CUR + j] - pz;
        float dist = sqrtf(fmaf(dz, dz, fmaf(dy, dy, dx * dx)));
        if (g_cur2pre[j] == i) sum += dist;
    }
    out[i] = sum / ups[i];
}

// ---------------------------------------------------------------------------
extern "C" void kernel_launch(void* const* d_in, const int* in_sizes, int n_in,
                              void* d_out, int out_size) {
    const float* pre = (const float*)d_in[0];   // (1, 3, 8192)
    const float* cur = (const float*)d_in[1];   // (1, 3, 16384)
    const float* ups = (const float*)d_in[2];   // (1, 8192)
    float* out = (float*)d_out;                 // (1, 8192)

    dim3 g1(N_CUR / NTHREADS, P1);
    k1_argmin<<<g1, NTHREADS>>>(pre, cur);

    dim3 g2(N_PRE / NTHREADS, P2);
    k2_topk<<<g2, NTHREADS>>>(pre, cur);        // independent of k1

    k1_reduce<<<N_CUR / NTHREADS, NTHREADS>>>();

    k3_final<<<N_PRE / NTHREADS, NTHREADS>>>(pre, cur, ups, out);
}

// round 2
// speedup vs baseline: 1.5185x; 1.5185x over previous
#include <cuda_runtime.h>
#include <math_constants.h>

#define N_PRE 8192
#define N_CUR 16384
#define KNN   8
#define P1    16                 // partitions over pre (argmin kernel)
#define P2    16                 // partitions over cur (top-8 kernel)
#define TILE1 (N_PRE / P1)       // 512 candidates / block
#define TILE2 (N_CUR / P2)       // 1024 candidates / block
#define NTHREADS 256
#define Q1    2                  // queries per thread in k1
#define NCAND (P2 * KNN)         // 128 merge candidates per pre point

// Scratch (no allocations allowed — device globals)
__device__ int   g_cur2pre[N_CUR];
__device__ float g_p1_key[P1 * N_CUR];
__device__ int   g_p1_idx[P1 * N_CUR];
__device__ float g_p2_key[N_PRE * NCAND];   // query-major for coalesced warp merge
__device__ int   g_p2_idx[N_PRE * NCAND];

// ---------------------------------------------------------------------------
// k1: partial argmin over a 512-wide pre partition for each cur point.
// Q1=2 queries per thread -> 2 independent min chains (ILP) + amortized LDS.
// Key: |p|^2 - 2 q.p (same ordering as sqdist). Index select is split from
// the key min (FMNMX carries the chain at lat 4; FSETP/SEL hang off it).
// ---------------------------------------------------------------------------
__global__ __launch_bounds__(NTHREADS)
void k1_argmin(const float* __restrict__ pre, const float* __restrict__ cur) {
    __shared__ float4 tile[TILE1];
    const int part = blockIdx.y;
    const int base = part * TILE1;

    for (int t = threadIdx.x; t < TILE1; t += NTHREADS) {
        float x = pre[base + t];
        float y = pre[N_PRE + base + t];
        float z = pre[2 * N_PRE + base + t];
        tile[t] = make_float4(x, y, z, fmaf(z, z, fmaf(y, y, x * x)));
    }
    __syncthreads();

    const int j0 = blockIdx.x * (NTHREADS * Q1) + threadIdx.x;
    const int j1 = j0 + NTHREADS;

    const float ax = cur[j0],             bx = cur[j1];
    const float ay = cur[N_CUR + j0],     by = cur[N_CUR + j1];
    const float az = cur[2 * N_CUR + j0], bz = cur[2 * N_CUR + j1];

    float ka = CUDART_INF_F, kb = CUDART_INF_F;
    int   ia = base,         ib = base;
#pragma unroll 8
    for (int t = 0; t < TILE1; ++t) {
        float4 c = tile[t];
        float da = fmaf(az, c.z, fmaf(ay, c.y, ax * c.x));
        float db = fmaf(bz, c.z, fmaf(by, c.y, bx * c.x));
        float keya = fmaf(-2.0f, da, c.w);
        float keyb = fmaf(-2.0f, db, c.w);
        if (keya < ka) ia = base + t;   // strict <: lowest index wins
        ka = fminf(keya, ka);
        if (keyb < kb) ib = base + t;
        kb = fminf(keyb, kb);
    }
    g_p1_key[part * N_CUR + j0] = ka;  g_p1_idx[part * N_CUR + j0] = ia;
    g_p1_key[part * N_CUR + j1] = kb;  g_p1_idx[part * N_CUR + j1] = ib;
}

// Reduce P1 partials (ascending partition order keeps the lowest-index tie rule).
__global__ __launch_bounds__(NTHREADS)
void k1_reduce() {
    const int j = blockIdx.x * NTHREADS + threadIdx.x;
    float bk = g_p1_key[j];
    int   bi = g_p1_idx[j];
#pragma unroll
    for (int p = 1; p < P1; ++p) {
        float k2 = g_p1_key[p * N_CUR + j];
        if (k2 < bk) { bk = k2; bi = g_p1_idx[p * N_CUR + j]; }
    }
    g_cur2pre[j] = bi;
}

// ---------------------------------------------------------------------------
// k2: partial top-8 over a 1024-wide cur partition for each pre point.
// Sorted 8-entry register list; insert path is rare-ish (~39/1024 per lane).
// Output query-major so the k3 warp merge reads coalesced.
// ---------------------------------------------------------------------------
__global__ __launch_bounds__(NTHREADS)
void k2_topk(const float* __restrict__ pre, const float* __restrict__ cur) {
    __shared__ float4 tile[TILE2];
    const int part = blockIdx.y;
    const int base = part * TILE2;

    for (int t = threadIdx.x; t < TILE2; t += NTHREADS) {
        float x = cur[base + t];
        float y = cur[N_CUR + base + t];
        float z = cur[2 * N_CUR + base + t];
        tile[t] = make_float4(x, y, z, fmaf(z, z, fmaf(y, y, x * x)));
    }
    __syncthreads();

    const int i = blockIdx.x * NTHREADS + threadIdx.x;
    const float qx = pre[i];
    const float qy = pre[N_PRE + i];
    const float qz = pre[2 * N_PRE + i];

    float d[KNN];
    int   id[KNN];
#pragma unroll
    for (int k = 0; k < KNN; ++k) { d[k] = CUDART_INF_F; id[k] = 0; }

#pragma unroll 4
    for (int t = 0; t < TILE2; ++t) {
        float4 c  = tile[t];
        float dot = fmaf(qz, c.z, fmaf(qy, c.y, qx * c.x));
        float key = fmaf(-2.0f, dot, c.w);
        if (key < d[KNN - 1]) {
            d[KNN - 1]  = key;
            id[KNN - 1] = base + t;
#pragma unroll
            for (int s = KNN - 1; s > 0; --s) {
                if (d[s] < d[s - 1]) {
                    float tf = d[s]; d[s] = d[s - 1]; d[s - 1] = tf;
                    int   ti = id[s]; id[s] = id[s - 1]; id[s - 1] = ti;
                }
            }
        }
    }
    const int rowbase = i * NCAND + part * KNN;
#pragma unroll
    for (int k = 0; k < KNN; ++k) {
        g_p2_key[rowbase + k] = d[k];
        g_p2_idx[rowbase + k] = id[k];
    }
}

// ---------------------------------------------------------------------------
// k3: warp per pre point. Lanes hold 4 candidates each (128 total), extract
// global top-8 via 8 rounds of shuffle argmin, then in-warp masked-dist sum.
// ---------------------------------------------------------------------------
__global__ __launch_bounds__(NTHREADS)
void k3_final(const float* __restrict__ pre, const float* __restrict__ cur,
              const float* __restrict__ ups, float* __restrict__ out) {
    const int gtid = blockIdx.x * NTHREADS + threadIdx.x;
    const int i    = gtid >> 5;          // query (8192 warps total, exact)
    const int lane = gtid & 31;

    // Coalesced candidate load: lane gets 4 consecutive slots.
    const float4 kv = *(const float4*)&g_p2_key[i * NCAND + lane * 4];
    const int4   iv = *(const int4*)  &g_p2_idx[i * NCAND + lane * 4];
    float ck[4] = { kv.x, kv.y, kv.z, kv.w };
    int   ci[4] = { iv.x, iv.y, iv.z, iv.w };

    int sel = -1;   // lane r (r<8) ends up holding the r-th extracted index
#pragma unroll
    for (int r = 0; r < KNN; ++r) {
        // lane-local min of 4
        float mk = ck[0]; int mi = ci[0];
        if (ck[1] < mk) { mk = ck[1]; mi = ci[1]; }
        if (ck[2] < mk) { mk = ck[2]; mi = ci[2]; }
        if (ck[3] < mk) { mk = ck[3]; mi = ci[3]; }
        // warp argmin
#pragma unroll
        for (int off = 16; off > 0; off >>= 1) {
            float ok = __shfl_down_sync(0xFFFFFFFFu, mk, off);
            int   oi = __shfl_down_sync(0xFFFFFFFFu, mi, off);
            if (ok < mk) { mk = ok; mi = oi; }
        }
        const int wi = __shfl_sync(0xFFFFFFFFu, mi, 0);
        if (lane == r) sel = wi;
        // invalidate winner (indices are globally unique)
#pragma unroll
        for (int s = 0; s < 4; ++s)
            if (ci[s] == wi) ck[s] = CUDART_INF_F;
    }

    const float px = pre[i];
    const float py = pre[N_PRE + i];
    const float pz = pre[2 * N_PRE + i];

    float val = 0.0f;
    if (lane < KNN) {
        const int j = sel;
        float dx = cur[j] - px;
        float dy = cur[N_CUR + j] - py;
        float dz = cur[2 * N_CUR + j] - pz;
        float dist = sqrtf(fmaf(dz, dz, fmaf(dy, dy, dx * dx)));
        val = (g_cur2pre[j] == i) ? dist : 0.0f;
    }
#pragma unroll
    for (int off = 4; off > 0; off >>= 1)
        val += __shfl_down_sync(0xFFFFFFFFu, val, off);

    if (lane == 0) out[i] = val / ups[i];
}

// ---------------------------------------------------------------------------
extern "C" void kernel_launch(void* const* d_in, const int* in_sizes, int n_in,
                              void* d_out, int out_size) {
    const float* pre = (const float*)d_in[0];   // (1, 3, 8192)
    const float* cur = (const float*)d_in[1];   // (1, 3, 16384)
    const float* ups = (const float*)d_in[2];   // (1, 8192)
    float* out = (float*)d_out;                 // (1, 8192)

    dim3 g1(N_CUR / (NTHREADS * Q1), P1);       // (32, 16)
    k1_argmin<<<g1, NTHREADS>>>(pre, cur);

    dim3 g2(N_PRE / NTHREADS, P2);              // (32, 16)
    k2_topk<<<g2, NTHREADS>>>(pre, cur);

    k1_reduce<<<N_CUR / NTHREADS, NTHREADS>>>();

    k3_final<<<(N_PRE * 32) / NTHREADS, NTHREADS>>>(pre, cur, ups, out);
}

// round 3
// speedup vs baseline: 1.7802x; 1.1723x over previous
#include <cuda_runtime.h>
#include <math_constants.h>

#define N_PRE 8192
#define N_CUR 16384
#define KNN   8
#define P1    16                 // partitions over pre (argmin kernel)
#define TILE1 (N_PRE / P1)       // 512 candidates / block
#define NTHREADS 256
#define Q1    2                  // queries per thread in k1

#define K2_TILE 2048             // cur candidates per smem tile in k2 (32KB)
#define K2_WARPS 8               // warps (= queries) per k2 block

// Scratch (no allocations allowed — device globals)
__device__ int   g_cur2pre[N_CUR];
__device__ float g_p1_key[P1 * N_CUR];
__device__ int   g_p1_idx[P1 * N_CUR];

// ---------------------------------------------------------------------------
// k1: partial argmin over a 512-wide pre partition for each cur point.
// Thread-per-query, broadcast candidate from SMEM, 2 queries/thread for ILP.
// Key: |p|^2 - 2 q.p  (same ordering as sqdist).
// ---------------------------------------------------------------------------
__global__ __launch_bounds__(NTHREADS)
void k1_argmin(const float* __restrict__ pre, const float* __restrict__ cur) {
    __shared__ float4 tile[TILE1];
    const int part = blockIdx.y;
    const int base = part * TILE1;

    for (int t = threadIdx.x; t < TILE1; t += NTHREADS) {
        float x = pre[base + t];
        float y = pre[N_PRE + base + t];
        float z = pre[2 * N_PRE + base + t];
        tile[t] = make_float4(x, y, z, fmaf(z, z, fmaf(y, y, x * x)));
    }
    __syncthreads();

    const int j0 = blockIdx.x * (NTHREADS * Q1) + threadIdx.x;
    const int j1 = j0 + NTHREADS;

    const float ax = cur[j0],             bx = cur[j1];
    const float ay = cur[N_CUR + j0],     by = cur[N_CUR + j1];
    const float az = cur[2 * N_CUR + j0], bz = cur[2 * N_CUR + j1];

    float ka = CUDART_INF_F, kb = CUDART_INF_F;
    int   ia = base,         ib = base;
#pragma unroll 8
    for (int t = 0; t < TILE1; ++t) {
        float4 c = tile[t];
        float da = fmaf(az, c.z, fmaf(ay, c.y, ax * c.x));
        float db = fmaf(bz, c.z, fmaf(by, c.y, bx * c.x));
        float keya = fmaf(-2.0f, da, c.w);
        float keyb = fmaf(-2.0f, db, c.w);
        if (keya < ka) ia = base + t;   // strict <: lowest index wins
        ka = fminf(keya, ka);
        if (keyb < kb) ib = base + t;
        kb = fminf(keyb, kb);
    }
    g_p1_key[part * N_CUR + j0] = ka;  g_p1_idx[part * N_CUR + j0] = ia;
    g_p1_key[part * N_CUR + j1] = kb;  g_p1_idx[part * N_CUR + j1] = ib;
}

// Reduce P1 partials (ascending partition order keeps lowest-index tie rule).
__global__ __launch_bounds__(NTHREADS)
void k1_reduce() {
    const int j = blockIdx.x * NTHREADS + threadIdx.x;
    float bk = g_p1_key[j];
    int   bi = g_p1_idx[j];
#pragma unroll
    for (int p = 1; p < P1; ++p) {
        float k2 = g_p1_key[p * N_CUR + j];
        if (k2 < bk) { bk = k2; bi = g_p1_idx[p * N_CUR + j]; }
    }
    g_cur2pre[j] = bi;
}

// ---------------------------------------------------------------------------
// k2: warp-cooperative exact top-8 over ALL 16384 cur points (no partitions),
// fused with the masked-mean-distance epilogue.
// One warp = one pre query. Lanes evaluate 32 candidates/iter; ballot vs the
// replicated 8th-best threshold; inserts are warp-uniform (every lane holds an
// identical sorted 8-list), so the divergent-insert tax of the old version is
// gone (~69 uniform insert events per 16384 candidates).
// Candidates are visited in ascending index order (lane order within ballot),
// so strict-< comparisons reproduce top_k's lowest-index tie-breaking.
// ---------------------------------------------------------------------------
__global__ __launch_bounds__(NTHREADS)
void k2_fused(const float* __restrict__ pre, const float* __restrict__ cur,
              const float* __restrict__ ups, float* __restrict__ out) {
    __shared__ float4 tile[K2_TILE];
    const int warpid = threadIdx.x >> 5;
    const int lane   = threadIdx.x & 31;
    const int i      = blockIdx.x * K2_WARPS + warpid;   // pre query

    const float qx = pre[i];
    const float qy = pre[N_PRE + i];
    const float qz = pre[2 * N_PRE + i];

    float d[KNN];
    int   id[KNN];
#pragma unroll
    for (int k = 0; k < KNN; ++k) { d[k] = CUDART_INF_F; id[k] = 0; }

    for (int tb = 0; tb < N_CUR; tb += K2_TILE) {
        // cooperative tile load (coalesced; cur is L2-resident)
        for (int t = threadIdx.x; t < K2_TILE; t += NTHREADS) {
            float x = cur[tb + t];
            float y = cur[N_CUR + tb + t];
            float z = cur[2 * N_CUR + tb + t];
            tile[t] = make_float4(x, y, z, fmaf(z, z, fmaf(y, y, x * x)));
        }
        __syncthreads();

        for (int t = 0; t < K2_TILE; t += 32) {
            float4 c  = tile[t + lane];
            float dot = fmaf(qz, c.z, fmaf(qy, c.y, qx * c.x));
            float key = fmaf(-2.0f, dot, c.w);
            unsigned m = __ballot_sync(0xFFFFFFFFu, key < d[KNN - 1]);
            while (m) {                         // uniform across warp
                const int l = __ffs(m) - 1;
                m &= m - 1;
                float kk = __shfl_sync(0xFFFFFFFFu, key, l);
                int   ji = tb + t + l;
                if (kk < d[KNN - 1]) {          // re-check vs tightened thresh
                    d[KNN - 1]  = kk;
                    id[KNN - 1] = ji;
#pragma unroll
                    for (int s = KNN - 1; s > 0; --s) {
                        if (d[s] < d[s - 1]) {
                            float tf = d[s]; d[s] = d[s - 1]; d[s - 1] = tf;
                            int   ti = id[s]; id[s] = id[s - 1]; id[s - 1] = ti;
                        }
                    }
                }
            }
        }
        __syncthreads();
    }

    // Fused epilogue: masked mean distance over the 8 neighbors.
    float val = 0.0f;
    if (lane < KNN) {
        const int j = id[lane];
        float dx = cur[j] - qx;
        float dy = cur[N_CUR + j] - qy;
        float dz = cur[2 * N_CUR + j] - qz;
        float dist = sqrtf(fmaf(dz, dz, fmaf(dy, dy, dx * dx)));
        val = (g_cur2pre[j] == i) ? dist : 0.0f;
    }
#pragma unroll
    for (int off = 4; off > 0; off >>= 1)
        val += __shfl_down_sync(0xFFFFFFFFu, val, off);

    if (lane == 0) out[i] = val / ups[i];
}

// ---------------------------------------------------------------------------
extern "C" void kernel_launch(void* const* d_in, const int* in_sizes, int n_in,
                              void* d_out, int out_size) {
    const float* pre = (const float*)d_in[0];   // (1, 3, 8192)
    const float* cur = (const float*)d_in[1];   // (1, 3, 16384)
    const float* ups = (const float*)d_in[2];   // (1, 8192)
    float* out = (float*)d_out;                 // (1, 8192)

    dim3 g1(N_CUR / (NTHREADS * Q1), P1);       // (32, 16)
    k1_argmin<<<g1, NTHREADS>>>(pre, cur);

    k1_reduce<<<N_CUR / NTHREADS, NTHREADS>>>();

    k2_fused<<<N_PRE / K2_WARPS, NTHREADS>>>(pre, cur, ups, out);
}

// round 4
// speedup vs baseline: 2.5717x; 1.4446x over previous
#include <cuda_runtime.h>
#include <math_constants.h>

#define N_PRE 8192
#define N_CUR 16384
#define KNN   8
#define NTHREADS 256

#define P1    16                  // partitions over pre (k1 argmin)
#define TILE1 (N_PRE / P1)        // 512
#define P2    16                  // partitions over cur (k2)
#define TILE2 (N_CUR / P2)        // 1024
#define CAP   64                  // admitted-candidate buffer per pre query

// Scratch (no allocations allowed — device globals)
__device__ int   g_cur2pre[N_CUR];
__device__ float g_p1_key[P1 * N_CUR];
__device__ int   g_p1_idx[P1 * N_CUR];
__device__ float g_p2_min[P2 * N_PRE];    // per-partition min key per pre query
__device__ float g_T[N_PRE];              // threshold (>= true 8th-smallest key)
__device__ int   g_cnt[N_PRE];
__device__ float g_bk[N_PRE * CAP];
__device__ int   g_bi[N_PRE * CAP];

// ---- packed f32x2 helpers ---------------------------------------------------
__device__ __forceinline__ unsigned long long packf2(float a, float b) {
    unsigned long long r;
    asm("mov.b64 %0, {%1,%2};" : "=l"(r) : "f"(a), "f"(b));
    return r;
}
__device__ __forceinline__ unsigned long long fma2(unsigned long long a,
                                                   unsigned long long b,
                                                   unsigned long long c) {
    unsigned long long d;
    asm("fma.rn.f32x2 %0, %1, %2, %3;" : "=l"(d) : "l"(a), "l"(b), "l"(c));
    return d;
}
__device__ __forceinline__ void unpackf2(unsigned long long v, float& lo, float& hi) {
    asm("mov.b64 {%0,%1}, %2;" : "=f"(lo), "=f"(hi) : "l"(v));
}

// key(c) for query q:  |c|^2 - 2 q.c  ==  fma(-2qz,z, fma(-2qy,y, fma(-2qx,x, n)))
// Same op sequence everywhere -> bitwise-identical recomputation.

// ---------------------------------------------------------------------------
// k1: argmin over a 512-wide pre partition for each cur point (2 queries/thr).
// Candidates stored as packed pairs in smem: xy = (x0,x1 | y0,y1), zn = (z0,z1 | n0,n1).
// ---------------------------------------------------------------------------
__global__ __launch_bounds__(NTHREADS)
void k1_argmin(const float* __restrict__ pre, const float* __restrict__ cur) {
    __shared__ ulonglong2 tXY[TILE1 / 2], tZN[TILE1 / 2];
    const int part = blockIdx.y;
    const int base = part * TILE1;

    for (int p = threadIdx.x; p < TILE1 / 2; p += NTHREADS) {
        int t0 = base + 2 * p, t1 = t0 + 1;
        float x0 = pre[t0],             x1 = pre[t1];
        float y0 = pre[N_PRE + t0],     y1 = pre[N_PRE + t1];
        float z0 = pre[2 * N_PRE + t0], z1 = pre[2 * N_PRE + t1];
        float n0 = fmaf(z0, z0, fmaf(y0, y0, x0 * x0));
        float n1 = fmaf(z1, z1, fmaf(y1, y1, x1 * x1));
        tXY[p] = make_ulonglong2(packf2(x0, x1), packf2(y0, y1));
        tZN[p] = make_ulonglong2(packf2(z0, z1), packf2(n0, n1));
    }
    __syncthreads();

    const int j0 = blockIdx.x * (NTHREADS * 2) + threadIdx.x;
    const int j1 = j0 + NTHREADS;

    const unsigned long long a2x = packf2(-2.0f * cur[j0], -2.0f * cur[j0]);
    const unsigned long long a2y = packf2(-2.0f * cur[N_CUR + j0], -2.0f * cur[N_CUR + j0]);
    const unsigned long long a2z = packf2(-2.0f * cur[2 * N_CUR + j0], -2.0f * cur[2 * N_CUR + j0]);
    const unsigned long long b2x = packf2(-2.0f * cur[j1], -2.0f * cur[j1]);
    const unsigned long long b2y = packf2(-2.0f * cur[N_CUR + j1], -2.0f * cur[N_CUR + j1]);
    const unsigned long long b2z = packf2(-2.0f * cur[2 * N_CUR + j1], -2.0f * cur[2 * N_CUR + j1]);

    float ka = CUDART_INF_F, kb = CUDART_INF_F;
    int   ia = base,         ib = base;
#pragma unroll 8
    for (int p = 0; p < TILE1 / 2; ++p) {
        ulonglong2 xy = tXY[p], zn = tZN[p];
        unsigned long long kA = fma2(a2z, zn.x, fma2(a2y, xy.y, fma2(a2x, xy.x, zn.y)));
        unsigned long long kB = fma2(b2z, zn.x, fma2(b2y, xy.y, fma2(b2x, xy.x, zn.y)));
        float lo, hi;
        unpackf2(kA, lo, hi);
        float mA = fminf(lo, hi);
        if (mA < ka) { ka = mA; ia = base + 2 * p + ((hi < lo) ? 1 : 0); }
        unpackf2(kB, lo, hi);
        float mB = fminf(lo, hi);
        if (mB < kb) { kb = mB; ib = base + 2 * p + ((hi < lo) ? 1 : 0); }
    }
    g_p1_key[part * N_CUR + j0] = ka;  g_p1_idx[part * N_CUR + j0] = ia;
    g_p1_key[part * N_CUR + j1] = kb;  g_p1_idx[part * N_CUR + j1] = ib;
}

__global__ __launch_bounds__(NTHREADS)
void k1_reduce() {
    const int j = blockIdx.x * NTHREADS + threadIdx.x;
    float bk = g_p1_key[j];
    int   bi = g_p1_idx[j];
#pragma unroll
    for (int p = 1; p < P1; ++p) {
        float k2 = g_p1_key[p * N_CUR + j];
        if (k2 < bk) { bk = k2; bi = g_p1_idx[p * N_CUR + j]; }
    }
    g_cur2pre[j] = bi;
}

// ---------------------------------------------------------------------------
// k2 pass A: per-partition MIN key over 1024 cur candidates (2 pre queries/thr).
// Pure FMNMX chains, no index tracking, no divergence.
// ---------------------------------------------------------------------------
__global__ __launch_bounds__(NTHREADS)
void k2_minpass(const float* __restrict__ pre, const float* __restrict__ cur) {
    __shared__ ulonglong2 tXY[TILE2 / 2], tZN[TILE2 / 2];
    const int part = blockIdx.y;
    const int base = part * TILE2;

    for (int p = threadIdx.x; p < TILE2 / 2; p += NTHREADS) {
        int t0 = base + 2 * p, t1 = t0 + 1;
        float x0 = cur[t0],             x1 = cur[t1];
        float y0 = cur[N_CUR + t0],     y1 = cur[N_CUR + t1];
        float z0 = cur[2 * N_CUR + t0], z1 = cur[2 * N_CUR + t1];
        float n0 = fmaf(z0, z0, fmaf(y0, y0, x0 * x0));
        float n1 = fmaf(z1, z1, fmaf(y1, y1, x1 * x1));
        tXY[p] = make_ulonglong2(packf2(x0, x1), packf2(y0, y1));
        tZN[p] = make_ulonglong2(packf2(z0, z1), packf2(n0, n1));
    }
    __syncthreads();

    const int i0 = blockIdx.x * (NTHREADS * 2) + threadIdx.x;
    const int i1 = i0 + NTHREADS;

    const unsigned long long a2x = packf2(-2.0f * pre[i0], -2.0f * pre[i0]);
    const unsigned long long a2y = packf2(-2.0f * pre[N_PRE + i0], -2.0f * pre[N_PRE + i0]);
    const unsigned long long a2z = packf2(-2.0f * pre[2 * N_PRE + i0], -2.0f * pre[2 * N_PRE + i0]);
    const unsigned long long b2x = packf2(-2.0f * pre[i1], -2.0f * pre[i1]);
    const unsigned long long b2y = packf2(-2.0f * pre[N_PRE + i1], -2.0f * pre[N_PRE + i1]);
    const unsigned long long b2z = packf2(-2.0f * pre[2 * N_PRE + i1], -2.0f * pre[2 * N_PRE + i1]);

    float ma = CUDART_INF_F, mb = CUDART_INF_F;
#pragma unroll 8
    for (int p = 0; p < TILE2 / 2; ++p) {
        ulonglong2 xy = tXY[p], zn = tZN[p];
        unsigned long long kA = fma2(a2z, zn.x, fma2(a2y, xy.y, fma2(a2x, xy.x, zn.y)));
        unsigned long long kB = fma2(b2z, zn.x, fma2(b2y, xy.y, fma2(b2x, xy.x, zn.y)));
        float lo, hi;
        unpackf2(kA, lo, hi); ma = fminf(ma, fminf(lo, hi));
        unpackf2(kB, lo, hi); mb = fminf(mb, fminf(lo, hi));
    }
    g_p2_min[part * N_PRE + i0] = ma;
    g_p2_min[part * N_PRE + i1] = mb;
}

// ---------------------------------------------------------------------------
// k2 threshold: T = 8th-smallest of the 16 partition minima.
// Proof: the 8 partitions with smallest minima each hold >=1 value <= T, so the
// global 8th-smallest key <= T  ->  admitting key <= T keeps the exact top-8.
// Also zeroes the admit counters.
// ---------------------------------------------------------------------------
__global__ __launch_bounds__(NTHREADS)
void k2_thresh() {
    const int i = blockIdx.x * NTHREADS + threadIdx.x;
    float v[P2];
#pragma unroll
    for (int p = 0; p < P2; ++p) v[p] = g_p2_min[p * N_PRE + i];
    float T = 0.0f;
#pragma unroll
    for (int r = 0; r < KNN; ++r) {          // 8 rounds of extract-min
        float mk = v[0]; int ms = 0;
#pragma unroll
        for (int p = 1; p < P2; ++p)
            if (v[p] < mk) { mk = v[p]; ms = p; }
        T = mk;
        v[ms] = CUDART_INF_F;
    }
    g_T[i]   = T;
    g_cnt[i] = 0;
}

// ---------------------------------------------------------------------------
// k2 pass B: re-scan; admit key <= T into a per-query buffer (rare: ~10-25).
// ---------------------------------------------------------------------------
__device__ __forceinline__ void admit(int q, float key, int idx) {
    int pos = atomicAdd(&g_cnt[q], 1);
    if (pos < CAP) { g_bk[q * CAP + pos] = key; g_bi[q * CAP + pos] = idx; }
}

__global__ __launch_bounds__(NTHREADS)
void k2_filter(const float* __restrict__ pre, const float* __restrict__ cur) {
    __shared__ ulonglong2 tXY[TILE2 / 2], tZN[TILE2 / 2];
    const int part = blockIdx.y;
    const int base = part * TILE2;

    for (int p = threadIdx.x; p < TILE2 / 2; p += NTHREADS) {
        int t0 = base + 2 * p, t1 = t0 + 1;
        float x0 = cur[t0],             x1 = cur[t1];
        float y0 = cur[N_CUR + t0],     y1 = cur[N_CUR + t1];
        float z0 = cur[2 * N_CUR + t0], z1 = cur[2 * N_CUR + t1];
        float n0 = fmaf(z0, z0, fmaf(y0, y0, x0 * x0));
        float n1 = fmaf(z1, z1, fmaf(y1, y1, x1 * x1));
        tXY[p] = make_ulonglong2(packf2(x0, x1), packf2(y0, y1));
        tZN[p] = make_ulonglong2(packf2(z0, z1), packf2(n0, n1));
    }
    __syncthreads();

    const int i0 = blockIdx.x * (NTHREADS * 2) + threadIdx.x;
    const int i1 = i0 + NTHREADS;

    const unsigned long long a2x = packf2(-2.0f * pre[i0], -2.0f * pre[i0]);
    const unsigned long long a2y = packf2(-2.0f * pre[N_PRE + i0], -2.0f * pre[N_PRE + i0]);
    const unsigned long long a2z = packf2(-2.0f * pre[2 * N_PRE + i0], -2.0f * pre[2 * N_PRE + i0]);
    const unsigned long long b2x = packf2(-2.0f * pre[i1], -2.0f * pre[i1]);
    const unsigned long long b2y = packf2(-2.0f * pre[N_PRE + i1], -2.0f * pre[N_PRE + i1]);
    const unsigned long long b2z = packf2(-2.0f * pre[2 * N_PRE + i1], -2.0f * pre[2 * N_PRE + i1]);
    const float Ta = g_T[i0];
    const float Tb = g_T[i1];

#pragma unroll 4
    for (int p = 0; p < TILE2 / 2; ++p) {
        ulonglong2 xy = tXY[p], zn = tZN[p];
        unsigned long long kA = fma2(a2z, zn.x, fma2(a2y, xy.y, fma2(a2x, xy.x, zn.y)));
        unsigned long long kB = fma2(b2z, zn.x, fma2(b2y, xy.y, fma2(b2x, xy.x, zn.y)));
        float lo, hi;
        unpackf2(kA, lo, hi);
        if (fminf(lo, hi) <= Ta) {
            if (lo <= Ta) admit(i0, lo, base + 2 * p);
            if (hi <= Ta) admit(i0, hi, base + 2 * p + 1);
        }
        unpackf2(kB, lo, hi);
        if (fminf(lo, hi) <= Tb) {
            if (lo <= Tb) admit(i1, lo, base + 2 * p);
            if (hi <= Tb) admit(i1, hi, base + 2 * p + 1);
        }
    }
}

// ---------------------------------------------------------------------------
// k2 final: warp per pre query. Exact top-8 of the admitted set via 8 rounds of
// lexicographic (key, idx) warp-argmin, then the masked mean-distance epilogue.
// ---------------------------------------------------------------------------
__global__ __launch_bounds__(NTHREADS)
void k2_final(const float* __restrict__ pre, const float* __restrict__ cur,
              const float* __restrict__ ups, float* __restrict__ out) {
    const int gtid = blockIdx.x * NTHREADS + threadIdx.x;
    const int i    = gtid >> 5;
    const int lane = gtid & 31;

    const int n = min(g_cnt[i], CAP);
    float c0 = (lane < n)      ? g_bk[i * CAP + lane]      : CUDART_INF_F;
    int   x0 = (lane < n)      ? g_bi[i * CAP + lane]      : 0x7FFFFFFF;
    float c1 = (lane + 32 < n) ? g_bk[i * CAP + lane + 32] : CUDART_INF_F;
    int   x1 = (lane + 32 < n) ? g_bi[i * CAP + lane + 32] : 0x7FFFFFFF;

    int   sel  = 0;
    float selk = CUDART_INF_F;
#pragma unroll
    for (int r = 0; r < KNN; ++r) {
        float mk = c0; int mi = x0;
        if (c1 < mk || (c1 == mk && x1 < mi)) { mk = c1; mi = x1; }
#pragma unroll
        for (int off = 16; off > 0; off >>= 1) {
            float ok = __shfl_down_sync(0xFFFFFFFFu, mk, off);
            int   oi = __shfl_down_sync(0xFFFFFFFFu, mi, off);
            if (ok < mk || (ok == mk && oi < mi)) { mk = ok; mi = oi; }
        }
        const int   wi = __shfl_sync(0xFFFFFFFFu, mi, 0);
        const float wk = __shfl_sync(0xFFFFFFFFu, mk, 0);
        if (lane == r) { sel = wi; selk = wk; }
        if (x0 == wi) c0 = CUDART_INF_F;
        if (x1 == wi) c1 = CUDART_INF_F;
    }

    const float px = pre[i];
    const float py = pre[N_PRE + i];
    const float pz = pre[2 * N_PRE + i];

    float val = 0.0f;
    if (lane < KNN && selk < CUDART_INF_F) {
        const int j = sel;
        float dx = cur[j] - px;
        float dy = cur[N_CUR + j] - py;
        float dz = cur[2 * N_CUR + j] - pz;
        float dist = sqrtf(fmaf(dz, dz, fmaf(dy, dy, dx * dx)));
        val = (g_cur2pre[j] == i) ? dist : 0.0f;
    }
#pragma unroll
    for (int off = 4; off > 0; off >>= 1)
        val += __shfl_down_sync(0xFFFFFFFFu, val, off);

    if (lane == 0) out[i] = val / ups[i];
}

// ---------------------------------------------------------------------------
extern "C" void kernel_launch(void* const* d_in, const int* in_sizes, int n_in,
                              void* d_out, int out_size) {
    const float* pre = (const float*)d_in[0];   // (1, 3, 8192)
    const float* cur = (const float*)d_in[1];   // (1, 3, 16384)
    const float* ups = (const float*)d_in[2];   // (1, 8192)
    float* out = (float*)d_out;                 // (1, 8192)

    dim3 g1(N_CUR / (NTHREADS * 2), P1);        // (32, 16)
    k1_argmin<<<g1, NTHREADS>>>(pre, cur);

    dim3 g2(N_PRE / (NTHREADS * 2), P2);        // (16, 16)
    k2_minpass<<<g2, NTHREADS>>>(pre, cur);

    k1_reduce<<<N_CUR / NTHREADS, NTHREADS>>>();
    k2_thresh<<<N_PRE / NTHREADS, NTHREADS>>>();

    k2_filter<<<g2, NTHREADS>>>(pre, cur);

    k2_final<<<(N_PRE * 32) / NTHREADS, NTHREADS>>>(pre, cur, ups, out);
}

// round 5
// speedup vs baseline: 3.1794x; 1.2363x over previous
#include <cuda_runtime.h>
#include <math_constants.h>

#define N_PRE 8192
#define N_CUR 16384
#define KNN   8
#define NTHREADS 256

#define P1    16                  // partitions over pre (k1 argmin)
#define TILE1 (N_PRE / P1)        // 512
#define P2    32                  // partitions over cur (k2)  [16 -> 32]
#define TILE2 (N_CUR / P2)        // 512
#define CAP   64                  // admitted-candidate buffer per pre query

// Scratch (no allocations allowed — device globals)
__device__ int   g_cur2pre[N_CUR];
__device__ float g_p1_key[P1 * N_CUR];
__device__ int   g_p1_idx[P1 * N_CUR];
__device__ float g_p2_min[P2 * N_PRE];    // per-partition min key per pre query
__device__ float g_T[N_PRE];              // threshold (>= true 8th-smallest key)
__device__ int   g_cnt[N_PRE];
__device__ float g_bk[N_PRE * CAP];
__device__ int   g_bi[N_PRE * CAP];

// ---- packed f32x2 helpers ---------------------------------------------------
__device__ __forceinline__ unsigned long long packf2(float a, float b) {
    unsigned long long r;
    asm("mov.b64 %0, {%1,%2};" : "=l"(r) : "f"(a), "f"(b));
    return r;
}
__device__ __forceinline__ unsigned long long fma2(unsigned long long a,
                                                   unsigned long long b,
                                                   unsigned long long c) {
    unsigned long long d;
    asm("fma.rn.f32x2 %0, %1, %2, %3;" : "=l"(d) : "l"(a), "l"(b), "l"(c));
    return d;
}
__device__ __forceinline__ void unpackf2(unsigned long long v, float& lo, float& hi) {
    asm("mov.b64 {%0,%1}, %2;" : "=f"(lo), "=f"(hi) : "l"(v));
}

// key(c) for query q:  |c|^2 - 2 q.c  (same ordering as sqdist; identical op
// sequence in every pass -> bitwise-identical recomputation).

// ---------------------------------------------------------------------------
// k1: argmin over a 512-wide pre partition for each cur point (2 queries/thr).
// ---------------------------------------------------------------------------
__global__ __launch_bounds__(NTHREADS)
void k1_argmin(const float* __restrict__ pre, const float* __restrict__ cur) {
    __shared__ ulonglong2 tXY[TILE1 / 2], tZN[TILE1 / 2];
    const int part = blockIdx.y;
    const int base = part * TILE1;

    for (int p = threadIdx.x; p < TILE1 / 2; p += NTHREADS) {
        int t0 = base + 2 * p, t1 = t0 + 1;
        float x0 = pre[t0],             x1 = pre[t1];
        float y0 = pre[N_PRE + t0],     y1 = pre[N_PRE + t1];
        float z0 = pre[2 * N_PRE + t0], z1 = pre[2 * N_PRE + t1];
        float n0 = fmaf(z0, z0, fmaf(y0, y0, x0 * x0));
        float n1 = fmaf(z1, z1, fmaf(y1, y1, x1 * x1));
        tXY[p] = make_ulonglong2(packf2(x0, x1), packf2(y0, y1));
        tZN[p] = make_ulonglong2(packf2(z0, z1), packf2(n0, n1));
    }
    __syncthreads();

    const int j0 = blockIdx.x * (NTHREADS * 2) + threadIdx.x;
    const int j1 = j0 + NTHREADS;

    const unsigned long long a2x = packf2(-2.0f * cur[j0], -2.0f * cur[j0]);
    const unsigned long long a2y = packf2(-2.0f * cur[N_CUR + j0], -2.0f * cur[N_CUR + j0]);
    const unsigned long long a2z = packf2(-2.0f * cur[2 * N_CUR + j0], -2.0f * cur[2 * N_CUR + j0]);
    const unsigned long long b2x = packf2(-2.0f * cur[j1], -2.0f * cur[j1]);
    const unsigned long long b2y = packf2(-2.0f * cur[N_CUR + j1], -2.0f * cur[N_CUR + j1]);
    const unsigned long long b2z = packf2(-2.0f * cur[2 * N_CUR + j1], -2.0f * cur[2 * N_CUR + j1]);

    float ka = CUDART_INF_F, kb = CUDART_INF_F;
    int   ia = base,         ib = base;
#pragma unroll 8
    for (int p = 0; p < TILE1 / 2; ++p) {
        ulonglong2 xy = tXY[p], zn = tZN[p];
        unsigned long long kA = fma2(a2z, zn.x, fma2(a2y, xy.y, fma2(a2x, xy.x, zn.y)));
        unsigned long long kB = fma2(b2z, zn.x, fma2(b2y, xy.y, fma2(b2x, xy.x, zn.y)));
        float lo, hi;
        unpackf2(kA, lo, hi);
        float mA = fminf(lo, hi);
        if (mA < ka) { ka = mA; ia = base + 2 * p + ((hi < lo) ? 1 : 0); }
        unpackf2(kB, lo, hi);
        float mB = fminf(lo, hi);
        if (mB < kb) { kb = mB; ib = base + 2 * p + ((hi < lo) ? 1 : 0); }
    }
    g_p1_key[part * N_CUR + j0] = ka;  g_p1_idx[part * N_CUR + j0] = ia;
    g_p1_key[part * N_CUR + j1] = kb;  g_p1_idx[part * N_CUR + j1] = ib;
}

// ---------------------------------------------------------------------------
// k2 pass A: per-partition MIN over a 512-wide cur tile (2 pre queries/thr).
// Two accumulators per query -> carried FMNMX chain halved.
// ---------------------------------------------------------------------------
__global__ __launch_bounds__(NTHREADS)
void k2_minpass(const float* __restrict__ pre, const float* __restrict__ cur) {
    __shared__ ulonglong2 tXY[TILE2 / 2], tZN[TILE2 / 2];
    const int part = blockIdx.y;
    const int base = part * TILE2;

    for (int p = threadIdx.x; p < TILE2 / 2; p += NTHREADS) {
        int t0 = base + 2 * p, t1 = t0 + 1;
        float x0 = cur[t0],             x1 = cur[t1];
        float y0 = cur[N_CUR + t0],     y1 = cur[N_CUR + t1];
        float z0 = cur[2 * N_CUR + t0], z1 = cur[2 * N_CUR + t1];
        float n0 = fmaf(z0, z0, fmaf(y0, y0, x0 * x0));
        float n1 = fmaf(z1, z1, fmaf(y1, y1, x1 * x1));
        tXY[p] = make_ulonglong2(packf2(x0, x1), packf2(y0, y1));
        tZN[p] = make_ulonglong2(packf2(z0, z1), packf2(n0, n1));
    }
    __syncthreads();

    const int i0 = blockIdx.x * (NTHREADS * 2) + threadIdx.x;
    const int i1 = i0 + NTHREADS;

    const unsigned long long a2x = packf2(-2.0f * pre[i0], -2.0f * pre[i0]);
    const unsigned long long a2y = packf2(-2.0f * pre[N_PRE + i0], -2.0f * pre[N_PRE + i0]);
    const unsigned long long a2z = packf2(-2.0f * pre[2 * N_PRE + i0], -2.0f * pre[2 * N_PRE + i0]);
    const unsigned long long b2x = packf2(-2.0f * pre[i1], -2.0f * pre[i1]);
    const unsigned long long b2y = packf2(-2.0f * pre[N_PRE + i1], -2.0f * pre[N_PRE + i1]);
    const unsigned long long b2z = packf2(-2.0f * pre[2 * N_PRE + i1], -2.0f * pre[2 * N_PRE + i1]);

    float ma0 = CUDART_INF_F, ma1 = CUDART_INF_F;
    float mb0 = CUDART_INF_F, mb1 = CUDART_INF_F;
#pragma unroll 8
    for (int p = 0; p < TILE2 / 2; ++p) {
        ulonglong2 xy = tXY[p], zn = tZN[p];
        unsigned long long kA = fma2(a2z, zn.x, fma2(a2y, xy.y, fma2(a2x, xy.x, zn.y)));
        unsigned long long kB = fma2(b2z, zn.x, fma2(b2y, xy.y, fma2(b2x, xy.x, zn.y)));
        float lo, hi;
        unpackf2(kA, lo, hi); ma0 = fminf(ma0, lo); ma1 = fminf(ma1, hi);
        unpackf2(kB, lo, hi); mb0 = fminf(mb0, lo); mb1 = fminf(mb1, hi);
    }
    g_p2_min[part * N_PRE + i0] = fminf(ma0, ma1);
    g_p2_min[part * N_PRE + i1] = fminf(mb0, mb1);
}

// ---------------------------------------------------------------------------
// combo: block-range split.
//  blocks [0,64):  k1 reduce -> g_cur2pre (ascending partition order = tie rule)
//  blocks [64,96): k2 threshold: T = 8th-smallest of 32 partition minima.
//    (>=8 partitions have min <= T, each holds >=1 key <= T -> exact superset)
// ---------------------------------------------------------------------------
__global__ __launch_bounds__(NTHREADS)
void k_combo() {
    if (blockIdx.x < N_CUR / NTHREADS) {
        const int j = blockIdx.x * NTHREADS + threadIdx.x;
        float bk = g_p1_key[j];
        int   bi = g_p1_idx[j];
#pragma unroll
        for (int p = 1; p < P1; ++p) {
            float k2 = g_p1_key[p * N_CUR + j];
            if (k2 < bk) { bk = k2; bi = g_p1_idx[p * N_CUR + j]; }
        }
        g_cur2pre[j] = bi;
    } else {
        const int i = (blockIdx.x - N_CUR / NTHREADS) * NTHREADS + threadIdx.x;
        float v[P2];
#pragma unroll
        for (int p = 0; p < P2; ++p) v[p] = g_p2_min[p * N_PRE + i];
        float T = 0.0f;
#pragma unroll
        for (int r = 0; r < KNN; ++r) {
            float mk = v[0]; int ms = 0;
#pragma unroll
            for (int p = 1; p < P2; ++p)
                if (v[p] < mk) { mk = v[p]; ms = p; }
            T = mk;
            v[ms] = CUDART_INF_F;
        }
        g_T[i]   = T;
        g_cnt[i] = 0;
    }
}

// ---------------------------------------------------------------------------
// k2 pass B: re-scan; admit key <= T (rare with the tighter 32-part threshold).
// ---------------------------------------------------------------------------
__device__ __forceinline__ void admit(int q, float key, int idx) {
    int pos = atomicAdd(&g_cnt[q], 1);
    if (pos < CAP) { g_bk[q * CAP + pos] = key; g_bi[q * CAP + pos] = idx; }
}

__global__ __launch_bounds__(NTHREADS)
void k2_filter(const float* __restrict__ pre, const float* __restrict__ cur) {
    __shared__ ulonglong2 tXY[TILE2 / 2], tZN[TILE2 / 2];
    const int part = blockIdx.y;
    const int base = part * TILE2;

    for (int p = threadIdx.x; p < TILE2 / 2; p += NTHREADS) {
        int t0 = base + 2 * p, t1 = t0 + 1;
        float x0 = cur[t0],             x1 = cur[t1];
        float y0 = cur[N_CUR + t0],     y1 = cur[N_CUR + t1];
        float z0 = cur[2 * N_CUR + t0], z1 = cur[2 * N_CUR + t1];
        float n0 = fmaf(z0, z0, fmaf(y0, y0, x0 * x0));
        float n1 = fmaf(z1, z1, fmaf(y1, y1, x1 * x1));
        tXY[p] = make_ulonglong2(packf2(x0, x1), packf2(y0, y1));
        tZN[p] = make_ulonglong2(packf2(z0, z1), packf2(n0, n1));
    }
    __syncthreads();

    const int i0 = blockIdx.x * (NTHREADS * 2) + threadIdx.x;
    const int i1 = i0 + NTHREADS;

    const unsigned long long a2x = packf2(-2.0f * pre[i0], -2.0f * pre[i0]);
    const unsigned long long a2y = packf2(-2.0f * pre[N_PRE + i0], -2.0f * pre[N_PRE + i0]);
    const unsigned long long a2z = packf2(-2.0f * pre[2 * N_PRE + i0], -2.0f * pre[2 * N_PRE + i0]);
    const unsigned long long b2x = packf2(-2.0f * pre[i1], -2.0f * pre[i1]);
    const unsigned long long b2y = packf2(-2.0f * pre[N_PRE + i1], -2.0f * pre[N_PRE + i1]);
    const unsigned long long b2z = packf2(-2.0f * pre[2 * N_PRE + i1], -2.0f * pre[2 * N_PRE + i1]);
    const float Ta = g_T[i0];
    const float Tb = g_T[i1];

#pragma unroll 4
    for (int p = 0; p < TILE2 / 2; ++p) {
        ulonglong2 xy = tXY[p], zn = tZN[p];
        unsigned long long kA = fma2(a2z, zn.x, fma2(a2y, xy.y, fma2(a2x, xy.x, zn.y)));
        unsigned long long kB = fma2(b2z, zn.x, fma2(b2y, xy.y, fma2(b2x, xy.x, zn.y)));
        float lo, hi;
        unpackf2(kA, lo, hi);
        if (fminf(lo, hi) <= Ta) {
            if (lo <= Ta) admit(i0, lo, base + 2 * p);
            if (hi <= Ta) admit(i0, hi, base + 2 * p + 1);
        }
        unpackf2(kB, lo, hi);
        if (fminf(lo, hi) <= Tb) {
            if (lo <= Tb) admit(i1, lo, base + 2 * p);
            if (hi <= Tb) admit(i1, hi, base + 2 * p + 1);
        }
    }
}

// ---------------------------------------------------------------------------
// k2 final: warp per pre query. Exact top-8 of the admitted set via 8 rounds of
// lexicographic (key, idx) warp-argmin, then the masked mean-distance epilogue.
// ---------------------------------------------------------------------------
__global__ __launch_bounds__(NTHREADS)
void k2_final(const float* __restrict__ pre, const float* __restrict__ cur,
              const float* __restrict__ ups, float* __restrict__ out) {
    const int gtid = blockIdx.x * NTHREADS + threadIdx.x;
    const int i    = gtid >> 5;
    const int lane = gtid & 31;

    const int n = min(g_cnt[i], CAP);
    float c0 = (lane < n)      ? g_bk[i * CAP + lane]      : CUDART_INF_F;
    int   x0 = (lane < n)      ? g_bi[i * CAP + lane]      : 0x7FFFFFFF;
    float c1 = (lane + 32 < n) ? g_bk[i * CAP + lane + 32] : CUDART_INF_F;
    int   x1 = (lane + 32 < n) ? g_bi[i * CAP + lane + 32] : 0x7FFFFFFF;

    int   sel  = 0;
    float selk = CUDART_INF_F;
#pragma unroll
    for (int r = 0; r < KNN; ++r) {
        float mk = c0; int mi = x0;
        if (c1 < mk || (c1 == mk && x1 < mi)) { mk = c1; mi = x1; }
#pragma unroll
        for (int off = 16; off > 0; off >>= 1) {
            float ok = __shfl_down_sync(0xFFFFFFFFu, mk, off);
            int   oi = __shfl_down_sync(0xFFFFFFFFu, mi, off);
            if (ok < mk || (ok == mk && oi < mi)) { mk = ok; mi = oi; }
        }
        const int   wi = __shfl_sync(0xFFFFFFFFu, mi, 0);
        const float wk = __shfl_sync(0xFFFFFFFFu, mk, 0);
        if (lane == r) { sel = wi; selk = wk; }
        if (x0 == wi) c0 = CUDART_INF_F;
        if (x1 == wi) c1 = CUDART_INF_F;
    }

    const float px = pre[i];
    const float py = pre[N_PRE + i];
    const float pz = pre[2 * N_PRE + i];

    float val = 0.0f;
    if (lane < KNN && selk < CUDART_INF_F) {
        const int j = sel;
        float dx = cur[j] - px;
        float dy = cur[N_CUR + j] - py;
        float dz = cur[2 * N_CUR + j] - pz;
        float dist = sqrtf(fmaf(dz, dz, fmaf(dy, dy, dx * dx)));
        val = (g_cur2pre[j] == i) ? dist : 0.0f;
    }
#pragma unroll
    for (int off = 4; off > 0; off >>= 1)
        val += __shfl_down_sync(0xFFFFFFFFu, val, off);

    if (lane == 0) out[i] = val / ups[i];
}

// ---------------------------------------------------------------------------
extern "C" void kernel_launch(void* const* d_in, const int* in_sizes, int n_in,
                              void* d_out, int out_size) {
    const float* pre = (const float*)d_in[0];   // (1, 3, 8192)
    const float* cur = (const float*)d_in[1];   // (1, 3, 16384)
    const float* ups = (const float*)d_in[2];   // (1, 8192)
    float* out = (float*)d_out;                 // (1, 8192)

    dim3 g1(N_CUR / (NTHREADS * 2), P1);        // (32, 16)
    k1_argmin<<<g1, NTHREADS>>>(pre, cur);

    dim3 g2(N_PRE / (NTHREADS * 2), P2);        // (16, 32)
    k2_minpass<<<g2, NTHREADS>>>(pre, cur);

    k_combo<<<N_CUR / NTHREADS + N_PRE / NTHREADS, NTHREADS>>>();

    k2_filter<<<g2, NTHREADS>>>(pre, cur);

    k2_final<<<(N_PRE * 32) / NTHREADS, NTHREADS>>>(pre, cur, ups, out);
}

// round 6
// speedup vs baseline: 4.0137x; 1.2624x over previous
#include <cuda_runtime.h>
#include <math_constants.h>

#define N_PRE 8192
#define N_CUR 16384
#define KNN   8
#define NTHREADS 256

#define P1    16                  // partitions over pre (k1 argmin)
#define TILE1 (N_PRE / P1)        // 512
#define P2    32                  // partitions over cur (k2) == warp width
#define TILE2 (N_CUR / P2)        // 512
#define CAP   64                  // admitted-candidate buffer per pre query
#define FWARPS 8                  // warps per filter block

// Scratch (no allocations allowed — device globals)
__device__ int    g_cur2pre[N_CUR];
__device__ float  g_p1_key[P1 * N_CUR];
__device__ int    g_p1_idx[P1 * N_CUR];
__device__ float  g_p2_min[P2 * N_PRE];   // per-partition min key per pre query
__device__ float  g_T[N_PRE];             // threshold (>= true 8th-smallest key)
__device__ float4 g_curp[N_CUR];          // packed cur: (x, y, z, |c|^2)

// ---- packed f32x2 helpers ---------------------------------------------------
__device__ __forceinline__ unsigned long long packf2(float a, float b) {
    unsigned long long r;
    asm("mov.b64 %0, {%1,%2};" : "=l"(r) : "f"(a), "f"(b));
    return r;
}
__device__ __forceinline__ unsigned long long fma2(unsigned long long a,
                                                   unsigned long long b,
                                                   unsigned long long c) {
    unsigned long long d;
    asm("fma.rn.f32x2 %0, %1, %2, %3;" : "=l"(d) : "l"(a), "l"(b), "l"(c));
    return d;
}
__device__ __forceinline__ void unpackf2(unsigned long long v, float& lo, float& hi) {
    asm("mov.b64 {%0,%1}, %2;" : "=f"(lo), "=f"(hi) : "l"(v));
}

// key(c) for query q:  fma(-2qz, z, fma(-2qy, y, fma(-2qx, x, |c|^2)))
// Identical op order in every pass (f32x2 lanes are IEEE fma.rn per lane)
// -> bitwise-identical recomputation across kernels.

// ---------------------------------------------------------------------------
// k1: argmin over a 512-wide pre partition for each cur point (2 queries/thr).
// ---------------------------------------------------------------------------
__global__ __launch_bounds__(NTHREADS)
void k1_argmin(const float* __restrict__ pre, const float* __restrict__ cur) {
    __shared__ ulonglong2 tXY[TILE1 / 2], tZN[TILE1 / 2];
    const int part = blockIdx.y;
    const int base = part * TILE1;

    for (int p = threadIdx.x; p < TILE1 / 2; p += NTHREADS) {
        int t0 = base + 2 * p, t1 = t0 + 1;
        float x0 = pre[t0],             x1 = pre[t1];
        float y0 = pre[N_PRE + t0],     y1 = pre[N_PRE + t1];
        float z0 = pre[2 * N_PRE + t0], z1 = pre[2 * N_PRE + t1];
        float n0 = fmaf(z0, z0, fmaf(y0, y0, x0 * x0));
        float n1 = fmaf(z1, z1, fmaf(y1, y1, x1 * x1));
        tXY[p] = make_ulonglong2(packf2(x0, x1), packf2(y0, y1));
        tZN[p] = make_ulonglong2(packf2(z0, z1), packf2(n0, n1));
    }
    __syncthreads();

    const int j0 = blockIdx.x * (NTHREADS * 2) + threadIdx.x;
    const int j1 = j0 + NTHREADS;

    const unsigned long long a2x = packf2(-2.0f * cur[j0], -2.0f * cur[j0]);
    const unsigned long long a2y = packf2(-2.0f * cur[N_CUR + j0], -2.0f * cur[N_CUR + j0]);
    const unsigned long long a2z = packf2(-2.0f * cur[2 * N_CUR + j0], -2.0f * cur[2 * N_CUR + j0]);
    const unsigned long long b2x = packf2(-2.0f * cur[j1], -2.0f * cur[j1]);
    const unsigned long long b2y = packf2(-2.0f * cur[N_CUR + j1], -2.0f * cur[N_CUR + j1]);
    const unsigned long long b2z = packf2(-2.0f * cur[2 * N_CUR + j1], -2.0f * cur[2 * N_CUR + j1]);

    float ka = CUDART_INF_F, kb = CUDART_INF_F;
    int   ia = base,         ib = base;
#pragma unroll 8
    for (int p = 0; p < TILE1 / 2; ++p) {
        ulonglong2 xy = tXY[p], zn = tZN[p];
        unsigned long long kA = fma2(a2z, zn.x, fma2(a2y, xy.y, fma2(a2x, xy.x, zn.y)));
        unsigned long long kB = fma2(b2z, zn.x, fma2(b2y, xy.y, fma2(b2x, xy.x, zn.y)));
        float lo, hi;
        unpackf2(kA, lo, hi);
        float mA = fminf(lo, hi);
        if (mA < ka) { ka = mA; ia = base + 2 * p + ((hi < lo) ? 1 : 0); }
        unpackf2(kB, lo, hi);
        float mB = fminf(lo, hi);
        if (mB < kb) { kb = mB; ib = base + 2 * p + ((hi < lo) ? 1 : 0); }
    }
    g_p1_key[part * N_CUR + j0] = ka;  g_p1_idx[part * N_CUR + j0] = ia;
    g_p1_key[part * N_CUR + j1] = kb;  g_p1_idx[part * N_CUR + j1] = ib;
}

// ---------------------------------------------------------------------------
// k2 pass A: per-partition MIN over a 512-wide cur tile (2 pre queries/thr).
// blockIdx.x==0 also writes the packed candidate array g_curp for its tile.
// ---------------------------------------------------------------------------
__global__ __launch_bounds__(NTHREADS)
void k2_minpass(const float* __restrict__ pre, const float* __restrict__ cur) {
    __shared__ ulonglong2 tXY[TILE2 / 2], tZN[TILE2 / 2];
    const int part = blockIdx.y;
    const int base = part * TILE2;

    for (int p = threadIdx.x; p < TILE2 / 2; p += NTHREADS) {
        int t0 = base + 2 * p, t1 = t0 + 1;
        float x0 = cur[t0],             x1 = cur[t1];
        float y0 = cur[N_CUR + t0],     y1 = cur[N_CUR + t1];
        float z0 = cur[2 * N_CUR + t0], z1 = cur[2 * N_CUR + t1];
        float n0 = fmaf(z0, z0, fmaf(y0, y0, x0 * x0));
        float n1 = fmaf(z1, z1, fmaf(y1, y1, x1 * x1));
        tXY[p] = make_ulonglong2(packf2(x0, x1), packf2(y0, y1));
        tZN[p] = make_ulonglong2(packf2(z0, z1), packf2(n0, n1));
        if (blockIdx.x == 0) {                 // publish packed candidates once
            g_curp[t0] = make_float4(x0, y0, z0, n0);
            g_curp[t1] = make_float4(x1, y1, z1, n1);
        }
    }
    __syncthreads();

    const int i0 = blockIdx.x * (NTHREADS * 2) + threadIdx.x;
    const int i1 = i0 + NTHREADS;

    const unsigned long long a2x = packf2(-2.0f * pre[i0], -2.0f * pre[i0]);
    const unsigned long long a2y = packf2(-2.0f * pre[N_PRE + i0], -2.0f * pre[N_PRE + i0]);
    const unsigned long long a2z = packf2(-2.0f * pre[2 * N_PRE + i0], -2.0f * pre[2 * N_PRE + i0]);
    const unsigned long long b2x = packf2(-2.0f * pre[i1], -2.0f * pre[i1]);
    const unsigned long long b2y = packf2(-2.0f * pre[N_PRE + i1], -2.0f * pre[N_PRE + i1]);
    const unsigned long long b2z = packf2(-2.0f * pre[2 * N_PRE + i1], -2.0f * pre[2 * N_PRE + i1]);

    float ma0 = CUDART_INF_F, ma1 = CUDART_INF_F;
    float mb0 = CUDART_INF_F, mb1 = CUDART_INF_F;
#pragma unroll 8
    for (int p = 0; p < TILE2 / 2; ++p) {
        ulonglong2 xy = tXY[p], zn = tZN[p];
        unsigned long long kA = fma2(a2z, zn.x, fma2(a2y, xy.y, fma2(a2x, xy.x, zn.y)));
        unsigned long long kB = fma2(b2z, zn.x, fma2(b2y, xy.y, fma2(b2x, xy.x, zn.y)));
        float lo, hi;
        unpackf2(kA, lo, hi); ma0 = fminf(ma0, lo); ma1 = fminf(ma1, hi);
        unpackf2(kB, lo, hi); mb0 = fminf(mb0, lo); mb1 = fminf(mb1, hi);
    }
    g_p2_min[part * N_PRE + i0] = fminf(ma0, ma1);
    g_p2_min[part * N_PRE + i1] = fminf(mb0, mb1);
}

// ---------------------------------------------------------------------------
// combo: blocks [0,64): k1 reduce -> g_cur2pre.  blocks [64,96): threshold
// T = 8th-smallest of 32 partition minima (exact-superset guarantee).
// ---------------------------------------------------------------------------
__global__ __launch_bounds__(NTHREADS)
void k_combo() {
    if (blockIdx.x < N_CUR / NTHREADS) {
        const int j = blockIdx.x * NTHREADS + threadIdx.x;
        float bk = g_p1_key[j];
        int   bi = g_p1_idx[j];
#pragma unroll
        for (int p = 1; p < P1; ++p) {
            float k2 = g_p1_key[p * N_CUR + j];
            if (k2 < bk) { bk = k2; bi = g_p1_idx[p * N_CUR + j]; }
        }
        g_cur2pre[j] = bi;
    } else {
        const int i = (blockIdx.x - N_CUR / NTHREADS) * NTHREADS + threadIdx.x;
        float v[P2];
#pragma unroll
        for (int p = 0; p < P2; ++p) v[p] = g_p2_min[p * N_PRE + i];
        float T = 0.0f;
#pragma unroll
        for (int r = 0; r < KNN; ++r) {
            float mk = v[0]; int ms = 0;
#pragma unroll
            for (int p = 1; p < P2; ++p)
                if (v[p] < mk) { mk = v[p]; ms = p; }
            T = mk;
            v[ms] = CUDART_INF_F;
        }
        g_T[i] = T;
    }
}

// ---------------------------------------------------------------------------
// k2 filter+final (fused): one warp per pre query.
// Lane p checks partition p's min vs T; warp scans ONLY qualifying partitions
// (~8 of 32), admits key<=T into a smem buffer via ballot/popc (no atomics),
// then exact top-8 via lexicographic (key, idx) warp-argmin + masked epilogue.
// ---------------------------------------------------------------------------
__global__ __launch_bounds__(NTHREADS)
void k2_filter_final(const float* __restrict__ pre, const float* __restrict__ ups,
                     float* __restrict__ out) {
    __shared__ float sk[FWARPS][CAP];
    __shared__ int   si[FWARPS][CAP];
    const int w    = threadIdx.x >> 5;
    const int lane = threadIdx.x & 31;
    const int i    = blockIdx.x * FWARPS + w;

    const float m2x = -2.0f * pre[i];
    const float m2y = -2.0f * pre[N_PRE + i];
    const float m2z = -2.0f * pre[2 * N_PRE + i];
    const float T   = g_T[i];

    // Qualifying partitions: lane p owns partition p (P2 == 32).
    const float pmin = g_p2_min[lane * N_PRE + i];
    unsigned pmask = __ballot_sync(0xFFFFFFFFu, pmin <= T);

    int cnt = 0;                                  // warp-uniform
    while (pmask) {
        const int p = __ffs(pmask) - 1;
        pmask &= pmask - 1;
        const int base = p * TILE2;
#pragma unroll 4
        for (int t = 0; t < TILE2; t += 32) {
            const float4 c = g_curp[base + t + lane];
            const float key = fmaf(m2z, c.z, fmaf(m2y, c.y, fmaf(m2x, c.x, c.w)));
            const bool adm = (key <= T);
            unsigned m = __ballot_sync(0xFFFFFFFFu, adm);
            if (m) {
                int pos = cnt + __popc(m & ((1u << lane) - 1u));
                if (adm && pos < CAP) { sk[w][pos] = key; si[w][pos] = base + t + lane; }
                cnt += __popc(m);
            }
        }
    }
    cnt = min(cnt, CAP);

    float c0 = (lane < cnt)      ? sk[w][lane]      : CUDART_INF_F;
    int   x0 = (lane < cnt)      ? si[w][lane]      : 0x7FFFFFFF;
    float c1 = (lane + 32 < cnt) ? sk[w][lane + 32] : CUDART_INF_F;
    int   x1 = (lane + 32 < cnt) ? si[w][lane + 32] : 0x7FFFFFFF;

    int   sel  = 0;
    float selk = CUDART_INF_F;
#pragma unroll
    for (int r = 0; r < KNN; ++r) {
        float mk = c0; int mi = x0;
        if (c1 < mk || (c1 == mk && x1 < mi)) { mk = c1; mi = x1; }
#pragma unroll
        for (int off = 16; off > 0; off >>= 1) {
            float ok = __shfl_down_sync(0xFFFFFFFFu, mk, off);
            int   oi = __shfl_down_sync(0xFFFFFFFFu, mi, off);
            if (ok < mk || (ok == mk && oi < mi)) { mk = ok; mi = oi; }
        }
        const int   wi = __shfl_sync(0xFFFFFFFFu, mi, 0);
        const float wk = __shfl_sync(0xFFFFFFFFu, mk, 0);
        if (lane == r) { sel = wi; selk = wk; }
        if (x0 == wi) c0 = CUDART_INF_F;
        if (x1 == wi) c1 = CUDART_INF_F;
    }

    const float px = pre[i];
    const float py = pre[N_PRE + i];
    const float pz = pre[2 * N_PRE + i];

    float val = 0.0f;
    if (lane < KNN && selk < CUDART_INF_F) {
        const int j = sel;
        const float4 c = g_curp[j];
        float dx = c.x - px, dy = c.y - py, dz = c.z - pz;
        float dist = sqrtf(fmaf(dz, dz, fmaf(dy, dy, dx * dx)));
        val = (g_cur2pre[j] == i) ? dist : 0.0f;
    }
#pragma unroll
    for (int off = 4; off > 0; off >>= 1)
        val += __shfl_down_sync(0xFFFFFFFFu, val, off);

    if (lane == 0) out[i] = val / ups[i];
}

// ---------------------------------------------------------------------------
extern "C" void kernel_launch(void* const* d_in, const int* in_sizes, int n_in,
                              void* d_out, int out_size) {
    const float* pre = (const float*)d_in[0];   // (1, 3, 8192)
    const float* cur = (const float*)d_in[1];   // (1, 3, 16384)
    const float* ups = (const float*)d_in[2];   // (1, 8192)
    float* out = (float*)d_out;                 // (1, 8192)

    dim3 g1(N_CUR / (NTHREADS * 2), P1);        // (32, 16)
    k1_argmin<<<g1, NTHREADS>>>(pre, cur);

    dim3 g2(N_PRE / (NTHREADS * 2), P2);        // (16, 32)
    k2_minpass<<<g2, NTHREADS>>>(pre, cur);

    k_combo<<<N_CUR / NTHREADS + N_PRE / NTHREADS, NTHREADS>>>();

    k2_filter_final<<<N_PRE / FWARPS, NTHREADS>>>(pre, ups, out);
}

// round 7
// speedup vs baseline: 4.8060x; 1.1974x over previous
#include <cuda_runtime.h>
#include <math_constants.h>

#define N_PRE 8192
#define N_CUR 16384
#define KNN   8
#define NTHREADS 256

#define P1    32                  // partitions over pre (k1)
#define TILE1 (N_PRE / P1)        // 256
#define P2    32                  // partitions over cur (k2)
#define TILE2 (N_CUR / P2)        // 512
#define NCHUNK 128                // fine chunks over cur (128 wide each)
#define CHUNK  (N_CUR / NCHUNK)   // 128
#define CAP   64
#define FWARPS 8

// Scratch (device globals; no allocations allowed)
__device__ int    g_cur2pre[N_CUR];
__device__ float  g_p1_min[P1 * N_CUR];    // per-partition min key (cur->pre)
__device__ float  g_cmin[NCHUNK * N_PRE];  // per-128-chunk min key (pre->cur)
__device__ float  g_T[N_PRE];
__device__ float4 g_prep[N_PRE];           // packed pre: (x,y,z,|p|^2)
__device__ float4 g_curp[N_CUR];           // packed cur: (x,y,z,|c|^2)

// ---- packed f32x2 helpers ---------------------------------------------------
__device__ __forceinline__ unsigned long long packf2(float a, float b) {
    unsigned long long r;
    asm("mov.b64 %0, {%1,%2};" : "=l"(r) : "f"(a), "f"(b));
    return r;
}
__device__ __forceinline__ unsigned long long fma2(unsigned long long a,
                                                   unsigned long long b,
                                                   unsigned long long c) {
    unsigned long long d;
    asm("fma.rn.f32x2 %0, %1, %2, %3;" : "=l"(d) : "l"(a), "l"(b), "l"(c));
    return d;
}
__device__ __forceinline__ void unpackf2(unsigned long long v, float& lo, float& hi) {
    asm("mov.b64 {%0,%1}, %2;" : "=f"(lo), "=f"(hi) : "l"(v));
}

// key(q, c) = fmaf(m2z, cz, fmaf(m2y, cy, fmaf(m2x, cx, |c|^2))), m2* = -2*q*.
// Same op order in packed (per-lane IEEE) and scalar recompute -> bitwise equal.

// ---------------------------------------------------------------------------
// Launch 1: merged min passes (index-free).
//  blockIdx.x <  P1     : k1 — min over a 256-wide PRE tile for 512 cur queries
//  blockIdx.x >= P1     : k2 — 128-chunk minima over a 512-wide CUR tile for
//                         512 pre queries (4 chunks of 128 per tile)
// ---------------------------------------------------------------------------
__global__ __launch_bounds__(NTHREADS)
void k_minpass(const float* __restrict__ pre, const float* __restrict__ cur) {
    __shared__ ulonglong2 tXY[256], tZN[256];
    const int tid = threadIdx.x;

    if (blockIdx.x < P1) {
        // ---------------- k1: cur -> pre partition minima ----------------
        const int part = blockIdx.x;
        const int base = part * TILE1;
        for (int p = tid; p < TILE1 / 2; p += NTHREADS) {
            int t0 = base + 2 * p, t1 = t0 + 1;
            float x0 = pre[t0],             x1 = pre[t1];
            float y0 = pre[N_PRE + t0],     y1 = pre[N_PRE + t1];
            float z0 = pre[2 * N_PRE + t0], z1 = pre[2 * N_PRE + t1];
            float n0 = fmaf(z0, z0, fmaf(y0, y0, x0 * x0));
            float n1 = fmaf(z1, z1, fmaf(y1, y1, x1 * x1));
            tXY[p] = make_ulonglong2(packf2(x0, x1), packf2(y0, y1));
            tZN[p] = make_ulonglong2(packf2(z0, z1), packf2(n0, n1));
            if (blockIdx.y == 0) {
                g_prep[t0] = make_float4(x0, y0, z0, n0);
                g_prep[t1] = make_float4(x1, y1, z1, n1);
            }
        }
        __syncthreads();

        const int j0 = blockIdx.y * (NTHREADS * 2) + tid;   // 16 y-blocks
        const int j1 = j0 + NTHREADS;
        const unsigned long long a2x = packf2(-2.0f * cur[j0], -2.0f * cur[j0]);
        const unsigned long long a2y = packf2(-2.0f * cur[N_CUR + j0], -2.0f * cur[N_CUR + j0]);
        const unsigned long long a2z = packf2(-2.0f * cur[2 * N_CUR + j0], -2.0f * cur[2 * N_CUR + j0]);
        const unsigned long long b2x = packf2(-2.0f * cur[j1], -2.0f * cur[j1]);
        const unsigned long long b2y = packf2(-2.0f * cur[N_CUR + j1], -2.0f * cur[N_CUR + j1]);
        const unsigned long long b2z = packf2(-2.0f * cur[2 * N_CUR + j1], -2.0f * cur[2 * N_CUR + j1]);

        float ma0 = CUDART_INF_F, ma1 = CUDART_INF_F;
        float mb0 = CUDART_INF_F, mb1 = CUDART_INF_F;
#pragma unroll 8
        for (int p = 0; p < TILE1 / 2; ++p) {
            ulonglong2 xy = tXY[p], zn = tZN[p];
            unsigned long long kA = fma2(a2z, zn.x, fma2(a2y, xy.y, fma2(a2x, xy.x, zn.y)));
            unsigned long long kB = fma2(b2z, zn.x, fma2(b2y, xy.y, fma2(b2x, xy.x, zn.y)));
            float lo, hi;
            unpackf2(kA, lo, hi); ma0 = fminf(ma0, lo); ma1 = fminf(ma1, hi);
            unpackf2(kB, lo, hi); mb0 = fminf(mb0, lo); mb1 = fminf(mb1, hi);
        }
        g_p1_min[part * N_CUR + j0] = fminf(ma0, ma1);
        g_p1_min[part * N_CUR + j1] = fminf(mb0, mb1);
    } else {
        // ---------------- k2: pre -> cur 128-chunk minima ----------------
        const int part = blockIdx.x - P1;
        const int base = part * TILE2;
        for (int p = tid; p < TILE2 / 2; p += NTHREADS) {
            int t0 = base + 2 * p, t1 = t0 + 1;
            float x0 = cur[t0],             x1 = cur[t1];
            float y0 = cur[N_CUR + t0],     y1 = cur[N_CUR + t1];
            float z0 = cur[2 * N_CUR + t0], z1 = cur[2 * N_CUR + t1];
            float n0 = fmaf(z0, z0, fmaf(y0, y0, x0 * x0));
            float n1 = fmaf(z1, z1, fmaf(y1, y1, x1 * x1));
            tXY[p] = make_ulonglong2(packf2(x0, x1), packf2(y0, y1));
            tZN[p] = make_ulonglong2(packf2(z0, z1), packf2(n0, n1));
            if (blockIdx.y == 0) {
                g_curp[t0] = make_float4(x0, y0, z0, n0);
                g_curp[t1] = make_float4(x1, y1, z1, n1);
            }
        }
        __syncthreads();

        if (blockIdx.y >= N_PRE / (NTHREADS * 2)) return;   // only 16 y-blocks used
        const int i0 = blockIdx.y * (NTHREADS * 2) + tid;
        const int i1 = i0 + NTHREADS;
        const unsigned long long a2x = packf2(-2.0f * pre[i0], -2.0f * pre[i0]);
        const unsigned long long a2y = packf2(-2.0f * pre[N_PRE + i0], -2.0f * pre[N_PRE + i0]);
        const unsigned long long a2z = packf2(-2.0f * pre[2 * N_PRE + i0], -2.0f * pre[2 * N_PRE + i0]);
        const unsigned long long b2x = packf2(-2.0f * pre[i1], -2.0f * pre[i1]);
        const unsigned long long b2y = packf2(-2.0f * pre[N_PRE + i1], -2.0f * pre[N_PRE + i1]);
        const unsigned long long b2z = packf2(-2.0f * pre[2 * N_PRE + i1], -2.0f * pre[2 * N_PRE + i1]);

#pragma unroll
        for (int c = 0; c < 4; ++c) {                 // 4 chunks of 128
            float ma0 = CUDART_INF_F, ma1 = CUDART_INF_F;
            float mb0 = CUDART_INF_F, mb1 = CUDART_INF_F;
#pragma unroll 8
            for (int p = c * 64; p < (c + 1) * 64; ++p) {
                ulonglong2 xy = tXY[p], zn = tZN[p];
                unsigned long long kA = fma2(a2z, zn.x, fma2(a2y, xy.y, fma2(a2x, xy.x, zn.y)));
                unsigned long long kB = fma2(b2z, zn.x, fma2(b2y, xy.y, fma2(b2x, xy.x, zn.y)));
                float lo, hi;
                unpackf2(kA, lo, hi); ma0 = fminf(ma0, lo); ma1 = fminf(ma1, hi);
                unpackf2(kB, lo, hi); mb0 = fminf(mb0, lo); mb1 = fminf(mb1, hi);
            }
            const int ch = part * 4 + c;
            g_cmin[ch * N_PRE + i0] = fminf(ma0, ma1);
            g_cmin[ch * N_PRE + i1] = fminf(mb0, mb1);
        }
    }
}

// ---------------------------------------------------------------------------
// Launch 2 (combo, warp-per-query):
//  blocks [0, 2048):  k1 argmin recovery — global min over 32 partition minima,
//    owner = lowest lane with pmin==gmin, rescan its 256-wide tile for the
//    first bitwise-equal key -> g_cur2pre. (lowest partition + first index
//    == global lowest index == argmin tie rule)
//  blocks [2048, 3072): threshold T = 8th-smallest of 128 chunk minima
//    (exact-superset: chunks ranked 1..8 each contain >=1 key <= T).
// ---------------------------------------------------------------------------
__global__ __launch_bounds__(NTHREADS)
void k_combo(const float* __restrict__ pre, const float* __restrict__ cur) {
    const int w    = threadIdx.x >> 5;
    const int lane = threadIdx.x & 31;

    if (blockIdx.x < N_CUR / FWARPS) {
        const int j = blockIdx.x * FWARPS + w;          // cur query
        const float pm = g_p1_min[lane * N_CUR + j];
        float gm = pm;
#pragma unroll
        for (int off = 16; off > 0; off >>= 1)
            gm = fminf(gm, __shfl_xor_sync(0xFFFFFFFFu, gm, off));
        const unsigned owners = __ballot_sync(0xFFFFFFFFu, pm == gm);
        const int opart = __ffs(owners) - 1;

        const float m2x = -2.0f * cur[j];
        const float m2y = -2.0f * cur[N_CUR + j];
        const float m2z = -2.0f * cur[2 * N_CUR + j];
        const int base = opart * TILE1;
        int found = -1;
#pragma unroll
        for (int t = 0; t < TILE1; t += 32) {
            if (found >= 0) break;                      // uniform
            const float4 c = g_prep[base + t + lane];
            const float key = fmaf(m2z, c.z, fmaf(m2y, c.y, fmaf(m2x, c.x, c.w)));
            unsigned m = __ballot_sync(0xFFFFFFFFu, key == gm);
            if (m) found = base + t + (__ffs(m) - 1);
        }
        if (lane == 0) g_cur2pre[j] = found;
    } else {
        const int i = (blockIdx.x - N_CUR / FWARPS) * FWARPS + w;   // pre query
        float v0 = g_cmin[lane * N_PRE + i];
        float v1 = g_cmin[(lane + 32) * N_PRE + i];
        float v2 = g_cmin[(lane + 64) * N_PRE + i];
        float v3 = g_cmin[(lane + 96) * N_PRE + i];
        float T = 0.0f;
#pragma unroll
        for (int r = 0; r < KNN; ++r) {
            float lmin = fminf(fminf(v0, v1), fminf(v2, v3));
            float gm = lmin;
#pragma unroll
            for (int off = 16; off > 0; off >>= 1)
                gm = fminf(gm, __shfl_xor_sync(0xFFFFFFFFu, gm, off));
            T = gm;
            const unsigned own = __ballot_sync(0xFFFFFFFFu, lmin == gm);
            if (lane == __ffs(own) - 1) {               // remove ONE instance
                if      (v0 == gm) v0 = CUDART_INF_F;
                else if (v1 == gm) v1 = CUDART_INF_F;
                else if (v2 == gm) v2 = CUDART_INF_F;
                else               v3 = CUDART_INF_F;
            }
        }
        if (lane == 0) g_T[i] = T;
    }
}

// ---------------------------------------------------------------------------
// Launch 3: filter + final, warp per pre query. Scan ONLY chunks whose min<=T
// (generically exactly 8 of 128 -> 1024 candidates); admit key<=T via
// ballot/popc into smem; exact top-8 via lexicographic warp-argmin; epilogue.
// ---------------------------------------------------------------------------
__global__ __launch_bounds__(NTHREADS)
void k_filter_final(const float* __restrict__ pre, const float* __restrict__ ups,
                    float* __restrict__ out) {
    __shared__ float sk[FWARPS][CAP];
    __shared__ int   si[FWARPS][CAP];
    const int w    = threadIdx.x >> 5;
    const int lane = threadIdx.x & 31;
    const int i    = blockIdx.x * FWARPS + w;

    const float m2x = -2.0f * pre[i];
    const float m2y = -2.0f * pre[N_PRE + i];
    const float m2z = -2.0f * pre[2 * N_PRE + i];
    const float T   = g_T[i];

    unsigned cm[4];
#pragma unroll
    for (int s = 0; s < 4; ++s) {
        const float q = g_cmin[(s * 32 + lane) * N_PRE + i];
        cm[s] = __ballot_sync(0xFFFFFFFFu, q <= T);
    }

    int cnt = 0;
#pragma unroll
    for (int s = 0; s < 4; ++s) {
        unsigned msk = cm[s];
        while (msk) {
            const int p = __ffs(msk) - 1;
            msk &= msk - 1;
            const int base = (s * 32 + p) * CHUNK;
#pragma unroll
            for (int t = 0; t < CHUNK; t += 32) {
                const float4 c = g_curp[base + t + lane];
                const float key = fmaf(m2z, c.z, fmaf(m2y, c.y, fmaf(m2x, c.x, c.w)));
                const bool adm = (key <= T);
                unsigned m = __ballot_sync(0xFFFFFFFFu, adm);
                if (m) {
                    int pos = cnt + __popc(m & ((1u << lane) - 1u));
                    if (adm && pos < CAP) { sk[w][pos] = key; si[w][pos] = base + t + lane; }
                    cnt += __popc(m);
                }
            }
        }
    }
    cnt = min(cnt, CAP);

    float c0 = (lane < cnt)      ? sk[w][lane]      : CUDART_INF_F;
    int   x0 = (lane < cnt)      ? si[w][lane]      : 0x7FFFFFFF;
    float c1 = (lane + 32 < cnt) ? sk[w][lane + 32] : CUDART_INF_F;
    int   x1 = (lane + 32 < cnt) ? si[w][lane + 32] : 0x7FFFFFFF;

    int   sel  = 0;
    float selk = CUDART_INF_F;
#pragma unroll
    for (int r = 0; r < KNN; ++r) {
        float mk = c0; int mi = x0;
        if (c1 < mk || (c1 == mk && x1 < mi)) { mk = c1; mi = x1; }
#pragma unroll
        for (int off = 16; off > 0; off >>= 1) {
            float ok = __shfl_down_sync(0xFFFFFFFFu, mk, off);
            int   oi = __shfl_down_sync(0xFFFFFFFFu, mi, off);
            if (ok < mk || (ok == mk && oi < mi)) { mk = ok; mi = oi; }
        }
        const int   wi = __shfl_sync(0xFFFFFFFFu, mi, 0);
        const float wk = __shfl_sync(0xFFFFFFFFu, mk, 0);
        if (lane == r) { sel = wi; selk = wk; }
        if (x0 == wi) c0 = CUDART_INF_F;
        if (x1 == wi) c1 = CUDART_INF_F;
    }

    const float px = pre[i];
    const float py = pre[N_PRE + i];
    const float pz = pre[2 * N_PRE + i];

    float val = 0.0f;
    if (lane < KNN && selk < CUDART_INF_F) {
        const int j = sel;
        const float4 c = g_curp[j];
        float dx = c.x - px, dy = c.y - py, dz = c.z - pz;
        float dist = sqrtf(fmaf(dz, dz, fmaf(dy, dy, dx * dx)));
        val = (g_cur2pre[j] == i) ? dist : 0.0f;
    }
#pragma unroll
    for (int off = 4; off > 0; off >>= 1)
        val += __shfl_down_sync(0xFFFFFFFFu, val, off);

    if (lane == 0) out[i] = val / ups[i];
}

// ---------------------------------------------------------------------------
extern "C" void kernel_launch(void* const* d_in, const int* in_sizes, int n_in,
                              void* d_out, int out_size) {
    const float* pre = (const float*)d_in[0];   // (1, 3, 8192)
    const float* cur = (const float*)d_in[1];   // (1, 3, 16384)
    const float* ups = (const float*)d_in[2];   // (1, 8192)
    float* out = (float*)d_out;                 // (1, 8192)

    dim3 gm(P1 + P2, N_CUR / (NTHREADS * 2));   // (64, 32); k2 uses y<16
    k_minpass<<<gm, NTHREADS>>>(pre, cur);

    k_combo<<<N_CUR / FWARPS + N_PRE / FWARPS, NTHREADS>>>(pre, cur);

    k_filter_final<<<N_PRE / FWARPS, NTHREADS>>>(pre, ups, out);
}